// round 3
// baseline (speedup 1.0000x reference)
#include <cuda_runtime.h>
#include <cuda_bf16.h>

#define ULL unsigned long long

__device__ __forceinline__ ULL pk2(float lo, float hi) {
    ULL r; asm("mov.b64 %0, {%1, %2};" : "=l"(r) : "f"(lo), "f"(hi)); return r;
}
__device__ __forceinline__ void unpk2(ULL v, float& lo, float& hi) {
    asm("mov.b64 {%0, %1}, %2;" : "=f"(lo), "=f"(hi) : "l"(v));
}
__device__ __forceinline__ ULL add2(ULL a, ULL b) {
    ULL r; asm("add.rn.f32x2 %0, %1, %2;" : "=l"(r) : "l"(a), "l"(b)); return r;
}
__device__ __forceinline__ void cpasync16(void* sptr, const void* gptr) {
    unsigned sa = (unsigned)__cvta_generic_to_shared(sptr);
    asm volatile("cp.async.cg.shared.global [%0], [%1], 16;" :: "r"(sa), "l"(gptr) : "memory");
}
__device__ __forceinline__ void cp_commit() {
    asm volatile("cp.async.commit_group;" ::: "memory");
}
template <int N>
__device__ __forceinline__ void cp_wait() {
    asm volatile("cp.async.wait_group %0;" :: "n"(N) : "memory");
}

// Tile: 16 states x 512 cells per block of 256 threads.
// Thread (ts = tid>>6 in [0,4), tc = tid&63 in [0,64)):
//   states ts*4 .. ts*4+3, cells tc + j*64 for j in [0,8).
// Dims processed as 16 float4 "dim-quads" (dq), in 8 double-buffered chunks of 2 dqs.
__global__ __launch_bounds__(256, 2) void PlaceCells_kernel(
    const float* __restrict__ x, const float* __restrict__ pc,
    float* __restrict__ out, int nstates)
{
    __shared__ float4 cs4[2048];     // 2 bufs x (2 dq x 512 cells), swizzled: 32 KB
    __shared__ float4 xs4[256];      // 16 states x 16 dq: 4 KB
    __shared__ float  wred[8][4];
    __shared__ float  wsum[8][4];

    const int tid = threadIdx.x;
    const int tc  = tid & 63;
    const int ts  = tid >> 6;
    const int bs  = blockIdx.x * 16;

    // ---- stage x tile (16 states x 64 dims = 256 float4) ----
    {
        int s = tid >> 4, q = tid & 15;
        xs4[tid] = reinterpret_cast<const float4*>(x)[(ULL)(bs + s) * 16 + q];
    }

    const float4* pc4 = reinterpret_cast<const float4*>(pc);

    // ---- prologue: issue chunk 0 ----
    {
        #pragma unroll
        for (int r = 0; r < 4; r++) {
            int idx = r * 256 + tid;          // 0..1023
            int cell = idx >> 1, dql = idx & 1;
            cpasync16(&cs4[dql * 512 + (cell ^ (dql << 2))],
                      &pc4[cell * 16 + dql]);
        }
        cp_commit();
    }

    ULL acc[4][8];
    #pragma unroll
    for (int i = 0; i < 4; i++)
        #pragma unroll
        for (int j = 0; j < 8; j++) acc[i][j] = 0ULL;

    const ULL ABSM = 0x7FFFFFFF7FFFFFFFULL;
    const ULL NEGM = 0x8000000080000000ULL;

    for (int k = 0; k < 8; k++) {
        __syncthreads();   // everyone done with buffer (k+1)&1 (chunk k-1); also covers xs4 on k=0
        if (k < 7) {
            int buf = (k + 1) & 1;
            #pragma unroll
            for (int r = 0; r < 4; r++) {
                int idx = r * 256 + tid;
                int cell = idx >> 1, dql = idx & 1;
                cpasync16(&cs4[buf * 1024 + dql * 512 + (cell ^ (dql << 2))],
                          &pc4[cell * 16 + (k + 1) * 2 + dql]);
            }
            cp_commit();
            cp_wait<1>();
        } else {
            cp_wait<0>();
        }
        __syncthreads();   // chunk k visible to all

        const int buf = k & 1;
        #pragma unroll
        for (int dql = 0; dql < 2; dql++) {
            const int dq = k * 2 + dql;
            ULL nx[8];
            #pragma unroll
            for (int i = 0; i < 4; i++) {
                float4 xv = xs4[(ts * 4 + i) * 16 + dq];   // warp-uniform broadcast
                nx[2 * i]     = pk2(xv.x, xv.y) ^ NEGM;
                nx[2 * i + 1] = pk2(xv.z, xv.w) ^ NEGM;
            }
            #pragma unroll
            for (int j = 0; j < 8; j++) {
                const int c = tc + j * 64;
                float4 cv = cs4[buf * 1024 + dql * 512 + (c ^ (dql << 2))];
                ULL clo = pk2(cv.x, cv.y);
                ULL chi = pk2(cv.z, cv.w);
                #pragma unroll
                for (int i = 0; i < 4; i++) {
                    ULL d0 = add2(clo, nx[2 * i])     & ABSM;   // |c - x| on 2 dims
                    ULL d1 = add2(chi, nx[2 * i + 1]) & ABSM;
                    acc[i][j] = add2(acc[i][j], d0);
                    acc[i][j] = add2(acc[i][j], d1);
                }
            }
        }
    }

    // ---- finalize logits: u = -0.5 * l1^2 ----
    float u[4][8];
    #pragma unroll
    for (int i = 0; i < 4; i++)
        #pragma unroll
        for (int j = 0; j < 8; j++) {
            float lo, hi; unpk2(acc[i][j], lo, hi);
            float l1 = lo + hi;
            u[i][j] = -0.5f * l1 * l1;
        }

    const int lane = tid & 31;
    const int w    = tid >> 5;           // warps 2*ts, 2*ts+1 share a state group

    // ---- row max ----
    float lm[4];
    #pragma unroll
    for (int i = 0; i < 4; i++) {
        float m = u[i][0];
        #pragma unroll
        for (int j = 1; j < 8; j++) m = fmaxf(m, u[i][j]);
        #pragma unroll
        for (int off = 16; off > 0; off >>= 1)
            m = fmaxf(m, __shfl_xor_sync(0xffffffffu, m, off));
        lm[i] = m;
    }
    if (lane == 0) {
        #pragma unroll
        for (int i = 0; i < 4; i++) wred[w][i] = lm[i];
    }
    __syncthreads();
    float mrow[4];
    #pragma unroll
    for (int i = 0; i < 4; i++)
        mrow[i] = fmaxf(wred[2 * ts][i], wred[2 * ts + 1][i]);

    // ---- exp + row sum ----
    float ls[4];
    #pragma unroll
    for (int i = 0; i < 4; i++) {
        float s = 0.0f;
        #pragma unroll
        for (int j = 0; j < 8; j++) {
            float e = __expf(u[i][j] - mrow[i]);
            u[i][j] = e;
            s += e;
        }
        #pragma unroll
        for (int off = 16; off > 0; off >>= 1)
            s += __shfl_xor_sync(0xffffffffu, s, off);
        ls[i] = s;
    }
    if (lane == 0) {
        #pragma unroll
        for (int i = 0; i < 4; i++) wsum[w][i] = ls[i];
    }
    __syncthreads();

    #pragma unroll
    for (int i = 0; i < 4; i++) {
        float inv = 1.0f / (wsum[2 * ts][i] + wsum[2 * ts + 1][i]);
        const int srow = bs + ts * 4 + i;
        #pragma unroll
        for (int j = 0; j < 8; j++)
            out[(ULL)srow * 512 + tc + j * 64] = u[i][j] * inv;
    }
}

extern "C" void kernel_launch(void* const* d_in, const int* in_sizes, int n_in,
                              void* d_out, int out_size) {
    const float* a = (const float*)d_in[0];
    const float* b = (const float*)d_in[1];
    // x is the larger tensor (8192*64), placeCells is 512*64
    const float* x  = (in_sizes[0] >= in_sizes[1]) ? a : b;
    const float* pc = (in_sizes[0] >= in_sizes[1]) ? b : a;
    int xsz = (in_sizes[0] >= in_sizes[1]) ? in_sizes[0] : in_sizes[1];
    int nstates = xsz / 64;          // 8192
    int grid = nstates / 16;         // 512 blocks

    PlaceCells_kernel<<<grid, 256>>>(x, pc, (float*)d_out, nstates);
}